// round 14
// baseline (speedup 1.0000x reference)
#include <cuda_runtime.h>
#include <math.h>

#define B 4
#define QL 4
#define HID 4096
#define NH 32
#define NKV 8
#define HD 128
#define GROUPS 4
#define PRIOR 4096
#define NROWS 16              // B*QL token rows
#define NQKV 6144             // NH*HD + 2*NKV*HD
#define QKV_KS 16
#define QKV_KRANGE (HID/QKV_KS)   // 256
#define WO_KS 32
#define WO_KRANGE (HID/WO_KS)     // 128
#define SPLITS 16
#define CHUNK (PRIOR/SPLITS)      // 256
#define SCALE 0.08838834764831845f  // 1/sqrt(128)

// ---------------- scratch (static device globals; no runtime alloc) --------
__device__ float g_qkv_part[QKV_KS][NROWS][NQKV];    // 6.3 MB
__device__ float g_q   [B*NKV][16][HD];
__device__ float g_kact[B*NKV][QL][HD];
__device__ float g_vact[B*NKV][QL][HD];
__device__ float g_po[B*NKV][SPLITS][16][HD];
__device__ float g_pm[B*NKV][SPLITS][16];
__device__ float g_pl[B*NKV][SPLITS][16];
__device__ float g_ctx[NROWS][NH*HD];
__device__ float g_wo_part[WO_KS][NROWS][HID];       // 8.4 MB

typedef unsigned long long u64;

__device__ __forceinline__ u64 pk2(float lo, float hi){
  u64 r; asm("mov.b64 %0,{%1,%2};" : "=l"(r) : "f"(lo), "f"(hi)); return r;
}
__device__ __forceinline__ void upk2(u64 v, float& lo, float& hi){
  asm("mov.b64 {%0,%1},%2;" : "=f"(lo), "=f"(hi) : "l"(v));
}
__device__ __forceinline__ void fma2(u64& d, u64 a, u64 b){
  asm("fma.rn.f32x2 %0,%1,%2,%0;" : "+l"(d) : "l"(a), "l"(b));
}

// ---------------- 1) fused QKV GEMV, K-split 16, 2 outputs/thread, unroll 16 -
__global__ __launch_bounds__(256) void qkv_gemm(
    const float* __restrict__ X, const float* __restrict__ wq,
    const float* __restrict__ wk, const float* __restrict__ wv)
{
  int ks = blockIdx.y;
  int k0 = ks * QKV_KRANGE;
  int np = blockIdx.x * 256 + threadIdx.x;   // n-pair index
  int n0 = np * 2;
  const float* W; int nn, ldn;
  if (n0 < NH*HD)            { W = wq; nn = n0;              ldn = NH*HD;  }
  else if (n0 < NH*HD+NKV*HD){ W = wk; nn = n0 - NH*HD;      ldn = NKV*HD; }
  else                       { W = wv; nn = n0 - NH*HD - NKV*HD; ldn = NKV*HD; }

  __shared__ __align__(16) float xs[QKV_KRANGE][16];   // 16KB
  for (int i = threadIdx.x; i < QKV_KRANGE*16; i += 256){
    int r = i >> 8, k = i & (QKV_KRANGE-1);
    xs[k][r] = X[r*HID + k0 + k];
  }
  __syncthreads();

  u64 acc0[8], acc1[8];
  #pragma unroll
  for (int i = 0; i < 8; i++){ acc0[i] = 0ull; acc1[i] = 0ull; }

  const float* Wp = W + (size_t)k0 * ldn + nn;
  #pragma unroll 16
  for (int k = 0; k < QKV_KRANGE; k++){
    float2 w2 = *(const float2*)Wp; Wp += ldn;
    u64 wa = pk2(w2.x, w2.x), wb = pk2(w2.y, w2.y);
    ulonglong2 xA = *(const ulonglong2*)&xs[k][0];
    ulonglong2 xB = *(const ulonglong2*)&xs[k][4];
    ulonglong2 xC = *(const ulonglong2*)&xs[k][8];
    ulonglong2 xD = *(const ulonglong2*)&xs[k][12];
    fma2(acc0[0], xA.x, wa); fma2(acc0[1], xA.y, wa);
    fma2(acc0[2], xB.x, wa); fma2(acc0[3], xB.y, wa);
    fma2(acc0[4], xC.x, wa); fma2(acc0[5], xC.y, wa);
    fma2(acc0[6], xD.x, wa); fma2(acc0[7], xD.y, wa);
    fma2(acc1[0], xA.x, wb); fma2(acc1[1], xA.y, wb);
    fma2(acc1[2], xB.x, wb); fma2(acc1[3], xB.y, wb);
    fma2(acc1[4], xC.x, wb); fma2(acc1[5], xC.y, wb);
    fma2(acc1[6], xD.x, wb); fma2(acc1[7], xD.y, wb);
  }
  #pragma unroll
  for (int i = 0; i < 8; i++){
    float l0,h0,l1,h1; upk2(acc0[i], l0, h0); upk2(acc1[i], l1, h1);
    *(float2*)&g_qkv_part[ks][2*i  ][n0] = make_float2(l0, l1);
    *(float2*)&g_qkv_part[ks][2*i+1][n0] = make_float2(h0, h1);
  }
}

// ---------------- 2) partial-reduce + RoPE (inline fp64) + scatter -----------
__global__ __launch_bounds__(256) void rope_scatter(const int* __restrict__ pos_w)
{
  int idx = blockIdx.x * 256 + threadIdx.x;     // 16*6144 total
  int row = idx / NQKV;
  int col = idx - row * NQKV;
  int b = row >> 2, qi = row & 3;

  float v = 0.f;
  #pragma unroll
  for (int s = 0; s < QKV_KS; s++) v += g_qkv_part[s][row][col];

  if (col >= NH*HD + NKV*HD){                   // V: no rope
    int c = col - (NH*HD + NKV*HD);
    int kvh = c >> 7, d = c & 127;
    g_vact[b*NKV + kvh][qi][d] = v;
    return;
  }
  int local = (col < NH*HD) ? col : col - NH*HD;
  int d = local & 127;
  int i = d & 63;
  int stride = (pos_w[1] == 0) ? 2 : 1;         // int64 (LE words) vs int32
  int p = pos_w[(b*QL + qi) * stride];
  double invf = exp(-((double)i / 64.0) * 13.815510557964274);  // 1e6^(-i/64)
  double ds, dc; sincos((double)p * invf, &ds, &dc);
  float c_ = (float)dc, s_ = (float)ds;

  int ocol = (d < 64) ? col + 64 : col - 64;
  float ov = 0.f;
  #pragma unroll
  for (int s = 0; s < QKV_KS; s++) ov += g_qkv_part[s][row][ocol];

  float out = (d < 64) ? (v*c_ - ov*s_) : (v*c_ + ov*s_);
  if (col < NH*HD){
    int h = col >> 7, kvh = h >> 2, g = h & 3;
    g_q[b*NKV + kvh][g*QL + qi][d] = out;
  } else {
    int kvh = (col - NH*HD) >> 7;
    g_kact[b*NKV + kvh][qi][d] = out;
  }
}

// ---------------- 3) split attention over PRIOR (exact R10/R13 best) ---------
__global__ __launch_bounds__(256) void attn_partial(
    const float* __restrict__ past_k, const float* __restrict__ past_v)
{
  int bk = blockIdx.y;       // b*NKV + kvh
  int sp = blockIdx.x;       // split
  int tid = threadIdx.x;
  int lane = tid & 31, wid = tid >> 5;

  __shared__ __align__(16) float qs[16][HD];     // scaled Q rows, 8KB
  __shared__ __align__(16) float ss[16][CHUNK];  // scores [row][key], 16KB
  __shared__ __align__(16) float red[8][8][HD];  // PV jslot partials, 32KB

  for (int i = tid; i < 16*HD; i += 256){
    int r = i >> 7, d = i & 127;
    qs[r][d] = g_q[bk][r][d] * SCALE;
  }
  __syncthreads();

  // ---- scores: 2 passes, 2 keys/thread; thread = (key group, 4-lane slice) --
  {
    int qt = tid & 3;          // dim slice within 4-lane group
    int keyg = tid >> 2;       // 0..63
    const float* Kbase = past_k + ((size_t)bk*PRIOR + (size_t)sp*CHUNK)*HD;
    #pragma unroll
    for (int p = 0; p < 2; p++){
      int j = p*128 + keyg;                 // keys j and j+64
      const ulonglong2* Kr0 = (const ulonglong2*)(Kbase + (size_t)j*HD) + qt;
      const ulonglong2* Kr1 = (const ulonglong2*)(Kbase + (size_t)(j+64)*HD) + qt;
      u64 acc0[16], acc1[16];
      #pragma unroll
      for (int r = 0; r < 16; r++){ acc0[r] = 0ull; acc1[r] = 0ull; }
      #pragma unroll 2
      for (int dd = 0; dd < 8; dd++){
        ulonglong2 ka = Kr0[dd*4];          // dims dd*16 + qt*4 ..+3
        ulonglong2 kb = Kr1[dd*4];
        int dim = dd*16 + qt*4;
        #pragma unroll
        for (int r = 0; r < 16; r++){
          ulonglong2 q2 = *(const ulonglong2*)&qs[r][dim];
          fma2(acc0[r], q2.x, ka.x);
          fma2(acc0[r], q2.y, ka.y);
          fma2(acc1[r], q2.x, kb.x);
          fma2(acc1[r], q2.y, kb.y);
        }
      }
      #pragma unroll
      for (int r = 0; r < 16; r++){
        float lo, hi; upk2(acc0[r], lo, hi);
        float s0 = lo + hi;
        upk2(acc1[r], lo, hi);
        float s1 = lo + hi;
        s0 += __shfl_xor_sync(~0u, s0, 1);
        s0 += __shfl_xor_sync(~0u, s0, 2);
        s1 += __shfl_xor_sync(~0u, s1, 1);
        s1 += __shfl_xor_sync(~0u, s1, 2);
        if (qt == 0){ ss[r][j] = s0; ss[r][j+64] = s1; }
      }
    }
  }
  __syncthreads();

  // ---- stats: warp owns 2 rows; max in registers; exp+sum one pass ---------
  #pragma unroll
  for (int rr = 0; rr < 2; rr++){
    int r = wid*2 + rr;
    float4* row = (float4*)ss[r];
    float4 a = row[lane], bq = row[lane+32];
    float m = fmaxf(fmaxf(fmaxf(a.x,a.y), fmaxf(a.z,a.w)),
                    fmaxf(fmaxf(bq.x,bq.y), fmaxf(bq.z,bq.w)));
    #pragma unroll
    for (int o = 16; o > 0; o >>= 1) m = fmaxf(m, __shfl_xor_sync(~0u, m, o));
    a.x = expf(a.x - m); a.y = expf(a.y - m); a.z = expf(a.z - m); a.w = expf(a.w - m);
    bq.x = expf(bq.x - m); bq.y = expf(bq.y - m); bq.z = expf(bq.z - m); bq.w = expf(bq.w - m);
    row[lane] = a; row[lane+32] = bq;
    float s = (a.x+a.y)+(a.z+a.w) + (bq.x+bq.y)+(bq.z+bq.w);
    #pragma unroll
    for (int o = 16; o > 0; o >>= 1) s += __shfl_xor_sync(~0u, s, o);
    if (lane == 0){ g_pm[bk][sp][r] = m; g_pl[bk][sp][r] = s; }
  }
  __syncthreads();

  // ---- PV: warp = (half, jslot); lane = 4-dim group -------------------------
  {
    int half = wid >> 2;          // rows half*8 .. +8
    int jslot = wid & 3;          // keys jslot*64 .. +64
    const float* Vb = past_v
        + ((size_t)bk*PRIOR + (size_t)sp*CHUNK + jslot*64)*HD + 4*lane;
    u64 acc[8][2];
    #pragma unroll
    for (int r = 0; r < 8; r++){ acc[r][0] = 0ull; acc[r][1] = 0ull; }

    for (int jj = 0; jj < 64; jj += 4){
      ulonglong2 w0 = *(const ulonglong2*)(Vb + (size_t)(jj+0)*HD);
      ulonglong2 w1 = *(const ulonglong2*)(Vb + (size_t)(jj+1)*HD);
      ulonglong2 w2 = *(const ulonglong2*)(Vb + (size_t)(jj+2)*HD);
      ulonglong2 w3 = *(const ulonglong2*)(Vb + (size_t)(jj+3)*HD);
      #pragma unroll
      for (int r = 0; r < 8; r++){
        ulonglong2 s4 = *(const ulonglong2*)&ss[half*8 + r][jslot*64 + jj];
        float s0, s1, s2, s3;
        upk2(s4.x, s0, s1); upk2(s4.y, s2, s3);
        u64 p0 = pk2(s0, s0), p1 = pk2(s1, s1);
        u64 p2 = pk2(s2, s2), p3 = pk2(s3, s3);
        fma2(acc[r][0], w0.x, p0); fma2(acc[r][1], w0.y, p0);
        fma2(acc[r][0], w1.x, p1); fma2(acc[r][1], w1.y, p1);
        fma2(acc[r][0], w2.x, p2); fma2(acc[r][1], w2.y, p2);
        fma2(acc[r][0], w3.x, p3); fma2(acc[r][1], w3.y, p3);
      }
    }
    #pragma unroll
    for (int r = 0; r < 8; r++){
      float4 o;
      upk2(acc[r][0], o.x, o.y);
      upk2(acc[r][1], o.z, o.w);
      *(float4*)&red[wid][r][4*lane] = o;
    }
  }
  __syncthreads();

  // ---- jslot reduction -> g_po ----------------------------------------------
  {
    int half2 = tid >> 7, d = tid & 127;
    #pragma unroll
    for (int r = 0; r < 8; r++){
      float o = red[half2*4+0][r][d] + red[half2*4+1][r][d]
              + red[half2*4+2][r][d] + red[half2*4+3][r][d];
      g_po[bk][sp][half2*8 + r][d] = o;
    }
  }
}

// ---------------- 4) LSE combine + active (causal) part ----------------------
__global__ __launch_bounds__(256) void attn_combine()
{
  int rg = blockIdx.x;       // 0..7 -> rows rg*2, rg*2+1
  int bk = blockIdx.y;
  int b = bk >> 3, kvh = bk & 7;
  int tid = threadIdx.x, lane = tid & 31, wid = tid >> 5;

  __shared__ float sc2[2][SPLITS], pa2[2][QL], invl[2];

  if (wid < 2){
    int r = rg*2 + wid, qi = r & 3;
    float m = (lane < SPLITS) ? g_pm[bk][lane][r] : -3.4e38f;
    #pragma unroll
    for (int o = 16; o > 0; o >>= 1) m = fmaxf(m, __shfl_xor_sync(~0u, m, o));
    float dots[QL];
    #pragma unroll
    for (int kq = 0; kq < QL; kq++){
      float a = g_q[bk][r][lane]      * g_kact[bk][kq][lane]
              + g_q[bk][r][lane+32]   * g_kact[bk][kq][lane+32]
              + g_q[bk][r][lane+64]   * g_kact[bk][kq][lane+64]
              + g_q[bk][r][lane+96]   * g_kact[bk][kq][lane+96];
      #pragma unroll
      for (int o = 16; o > 0; o >>= 1) a += __shfl_xor_sync(~0u, a, o);
      dots[kq] = a * SCALE;
      if (kq <= qi) m = fmaxf(m, dots[kq]);
    }
    float contrib = 0.f;
    if (lane < SPLITS){
      float e = expf(g_pm[bk][lane][r] - m);
      sc2[wid][lane] = e;
      contrib = g_pl[bk][lane][r] * e;
    }
    if (lane < QL){
      float ea = (lane <= qi) ? expf(dots[lane] - m) : 0.f;
      pa2[wid][lane] = ea;
      contrib += ea;
    }
    #pragma unroll
    for (int o = 16; o > 0; o >>= 1) contrib += __shfl_xor_sync(~0u, contrib, o);
    if (lane == 0) invl[wid] = 1.f / contrib;
  }
  __syncthreads();

  int half = tid >> 7, d = tid & 127;
  int r = rg*2 + half;
  float o = 0.f;
  #pragma unroll
  for (int s = 0; s < SPLITS; s++) o += g_po[bk][s][r][d] * sc2[half][s];
  #pragma unroll
  for (int kq = 0; kq < QL; kq++) o += pa2[half][kq] * g_vact[bk][kq][d];
  o *= invl[half];
  int g = r >> 2, qi2 = r & 3, h = kvh*GROUPS + g;
  g_ctx[b*QL + qi2][h*HD + d] = o;
}

// ---------------- 5) WO GEMV, K-split 32, 2 outputs/thread, unroll 16 --------
__global__ __launch_bounds__(256) void wo_gemm(const float* __restrict__ W)
{
  int ks = blockIdx.y;
  int k0 = ks * WO_KRANGE;
  int np = blockIdx.x * 256 + threadIdx.x;
  int n0 = np * 2;

  __shared__ __align__(16) float xs[WO_KRANGE][16];   // 8KB
  for (int i = threadIdx.x; i < WO_KRANGE*16; i += 256){
    int r = i >> 7, k = i & (WO_KRANGE-1);
    xs[k][r] = g_ctx[r][k0 + k];
  }
  __syncthreads();

  u64 acc0[8], acc1[8];
  #pragma unroll
  for (int i = 0; i < 8; i++){ acc0[i] = 0ull; acc1[i] = 0ull; }

  const float* Wp = W + (size_t)k0 * HID + n0;
  #pragma unroll 16
  for (int k = 0; k < WO_KRANGE; k++){
    float2 w2 = *(const float2*)Wp; Wp += HID;
    u64 wa = pk2(w2.x, w2.x), wb = pk2(w2.y, w2.y);
    ulonglong2 xA = *(const ulonglong2*)&xs[k][0];
    ulonglong2 xB = *(const ulonglong2*)&xs[k][4];
    ulonglong2 xC = *(const ulonglong2*)&xs[k][8];
    ulonglong2 xD = *(const ulonglong2*)&xs[k][12];
    fma2(acc0[0], xA.x, wa); fma2(acc0[1], xA.y, wa);
    fma2(acc0[2], xB.x, wa); fma2(acc0[3], xB.y, wa);
    fma2(acc0[4], xC.x, wa); fma2(acc0[5], xC.y, wa);
    fma2(acc0[6], xD.x, wa); fma2(acc0[7], xD.y, wa);
    fma2(acc1[0], xA.x, wb); fma2(acc1[1], xA.y, wb);
    fma2(acc1[2], xB.x, wb); fma2(acc1[3], xB.y, wb);
    fma2(acc1[4], xC.x, wb); fma2(acc1[5], xC.y, wb);
    fma2(acc1[6], xD.x, wb); fma2(acc1[7], xD.y, wb);
  }
  #pragma unroll
  for (int i = 0; i < 8; i++){
    float l0,h0,l1,h1; upk2(acc0[i], l0, h0); upk2(acc1[i], l1, h1);
    *(float2*)&g_wo_part[ks][2*i  ][n0] = make_float2(l0, l1);
    *(float2*)&g_wo_part[ks][2*i+1][n0] = make_float2(h0, h1);
  }
}

// ---------------- 6) reduce partials -> d_out --------------------------------
__global__ __launch_bounds__(256) void wo_reduce(float* __restrict__ out)
{
  int idx = blockIdx.x * 256 + threadIdx.x;  // 65536 total
  const float* base = (const float*)g_wo_part;
  float v = 0.f;
  #pragma unroll
  for (int s = 0; s < WO_KS; s++) v += base[(size_t)s * (NROWS*HID) + idx];
  out[idx] = v;
}

// ---------------- launch ------------------------------------------------------
extern "C" void kernel_launch(void* const* d_in, const int* in_sizes, int n_in,
                              void* d_out, int out_size)
{
  const float* hs     = (const float*)d_in[0];
  const float* past_k = (const float*)d_in[1];
  const float* past_v = (const float*)d_in[2];
  const float* wq     = (const float*)d_in[3];
  const float* wk     = (const float*)d_in[4];
  const float* wv     = (const float*)d_in[5];
  const float* wo     = (const float*)d_in[6];
  const int* pos_w    = (const int*)d_in[n_in - 1];   // int32 or int64 words
  float* out = (float*)d_out;

  qkv_gemm   <<<dim3(NQKV/512, QKV_KS), 256>>>(hs, wq, wk, wv);
  rope_scatter<<<(NROWS*NQKV)/256, 256>>>(pos_w);
  attn_partial<<<dim3(SPLITS, B*NKV), 256>>>(past_k, past_v);
  attn_combine<<<dim3(8, B*NKV), 256>>>();
  wo_gemm    <<<dim3(HID/512, WO_KS), 256>>>(wo);
  wo_reduce  <<<(NROWS*HID)/256, 256>>>(out);
}

// round 15
// speedup vs baseline: 1.0906x; 1.0906x over previous
#include <cuda_runtime.h>
#include <math.h>

#define B 4
#define QL 4
#define HID 4096
#define NH 32
#define NKV 8
#define HD 128
#define GROUPS 4
#define PRIOR 4096
#define NROWS 16              // B*QL token rows
#define NQKV 6144             // NH*HD + 2*NKV*HD
#define QKV_KS 32
#define QKV_KRANGE (HID/QKV_KS)   // 128
#define WO_KS 32
#define WO_KRANGE (HID/WO_KS)     // 128
#define SPLITS 16
#define CHUNK (PRIOR/SPLITS)      // 256
#define SCALE 0.08838834764831845f  // 1/sqrt(128)

// ---------------- scratch (static device globals; no runtime alloc) --------
__device__ float g_qkv_part[QKV_KS][NROWS][NQKV];
__device__ float g_q   [B*NKV][16][HD];
__device__ float g_kact[B*NKV][QL][HD];
__device__ float g_vact[B*NKV][QL][HD];
__device__ float g_po[B*NKV][SPLITS][16][HD];
__device__ float g_pm[B*NKV][SPLITS][16];
__device__ float g_pl[B*NKV][SPLITS][16];
__device__ float g_ctx[NROWS][NH*HD];
__device__ float g_wo_part[WO_KS][NROWS][HID];

typedef unsigned long long u64;

__device__ __forceinline__ u64 pk2(float lo, float hi){
  u64 r; asm("mov.b64 %0,{%1,%2};" : "=l"(r) : "f"(lo), "f"(hi)); return r;
}
__device__ __forceinline__ void upk2(u64 v, float& lo, float& hi){
  asm("mov.b64 {%0,%1},%2;" : "=f"(lo), "=f"(hi) : "l"(v));
}
__device__ __forceinline__ void fma2(u64& d, u64 a, u64 b){
  asm("fma.rn.f32x2 %0,%1,%2,%0;" : "+l"(d) : "l"(a), "l"(b));
}

// ---------------- 1) fused QKV GEMV, K-split 32, float4 W loads, unroll 16 ---
__global__ __launch_bounds__(256) void qkv_gemm(
    const float* __restrict__ X, const float* __restrict__ wq,
    const float* __restrict__ wk, const float* __restrict__ wv)
{
  int ks = blockIdx.y;
  int k0 = ks * QKV_KRANGE;
  int np = blockIdx.x * 256 + threadIdx.x;   // n-quad index
  int n0 = np * 4;
  const float* W; int nn, ldn;
  if (n0 < NH*HD)            { W = wq; nn = n0;              ldn = NH*HD;  }
  else if (n0 < NH*HD+NKV*HD){ W = wk; nn = n0 - NH*HD;      ldn = NKV*HD; }
  else                       { W = wv; nn = n0 - NH*HD - NKV*HD; ldn = NKV*HD; }

  __shared__ __align__(16) float xs[QKV_KRANGE][16];
  for (int i = threadIdx.x; i < QKV_KRANGE*16; i += 256){
    int r = i >> 7, k = i & (QKV_KRANGE-1);
    xs[k][r] = X[r*HID + k0 + k];
  }
  __syncthreads();

  u64 acc[4][8];
  #pragma unroll
  for (int o = 0; o < 4; o++)
    #pragma unroll
    for (int i = 0; i < 8; i++) acc[o][i] = 0ull;

  const float4* Wp = (const float4*)(W + (size_t)k0 * ldn + nn);
  int ld4 = ldn >> 2;
  #pragma unroll 16
  for (int k = 0; k < QKV_KRANGE; k++){
    float4 w4 = *Wp; Wp += ld4;
    u64 wb[4];
    wb[0] = pk2(w4.x, w4.x); wb[1] = pk2(w4.y, w4.y);
    wb[2] = pk2(w4.z, w4.z); wb[3] = pk2(w4.w, w4.w);
    ulonglong2 xA = *(const ulonglong2*)&xs[k][0];
    ulonglong2 xB = *(const ulonglong2*)&xs[k][4];
    ulonglong2 xC = *(const ulonglong2*)&xs[k][8];
    ulonglong2 xD = *(const ulonglong2*)&xs[k][12];
    #pragma unroll
    for (int o = 0; o < 4; o++){
      fma2(acc[o][0], xA.x, wb[o]); fma2(acc[o][1], xA.y, wb[o]);
      fma2(acc[o][2], xB.x, wb[o]); fma2(acc[o][3], xB.y, wb[o]);
      fma2(acc[o][4], xC.x, wb[o]); fma2(acc[o][5], xC.y, wb[o]);
      fma2(acc[o][6], xD.x, wb[o]); fma2(acc[o][7], xD.y, wb[o]);
    }
  }
  #pragma unroll
  for (int i = 0; i < 8; i++){
    float lo[4], hi[4];
    #pragma unroll
    for (int o = 0; o < 4; o++) upk2(acc[o][i], lo[o], hi[o]);
    *(float4*)&g_qkv_part[ks][2*i  ][n0] = make_float4(lo[0], lo[1], lo[2], lo[3]);
    *(float4*)&g_qkv_part[ks][2*i+1][n0] = make_float4(hi[0], hi[1], hi[2], hi[3]);
  }
}

// ---------------- 2) partial-reduce + RoPE (inline fp64) + scatter -----------
__global__ __launch_bounds__(256) void rope_scatter(const int* __restrict__ pos_w)
{
  int idx = blockIdx.x * 256 + threadIdx.x;     // 16*6144 total
  int row = idx / NQKV;
  int col = idx - row * NQKV;
  int b = row >> 2, qi = row & 3;

  float v = 0.f;
  #pragma unroll
  for (int s = 0; s < QKV_KS; s++) v += g_qkv_part[s][row][col];

  if (col >= NH*HD + NKV*HD){                   // V: no rope
    int c = col - (NH*HD + NKV*HD);
    int kvh = c >> 7, d = c & 127;
    g_vact[b*NKV + kvh][qi][d] = v;
    return;
  }
  int local = (col < NH*HD) ? col : col - NH*HD;
  int d = local & 127;
  int i = d & 63;
  int stride = (pos_w[1] == 0) ? 2 : 1;         // int64 (LE words) vs int32
  int p = pos_w[(b*QL + qi) * stride];
  double invf = exp(-((double)i / 64.0) * 13.815510557964274);  // 1e6^(-i/64)
  double ds, dc; sincos((double)p * invf, &ds, &dc);
  float c_ = (float)dc, s_ = (float)ds;

  int ocol = (d < 64) ? col + 64 : col - 64;
  float ov = 0.f;
  #pragma unroll
  for (int s = 0; s < QKV_KS; s++) ov += g_qkv_part[s][row][ocol];

  float out = (d < 64) ? (v*c_ - ov*s_) : (v*c_ + ov*s_);
  if (col < NH*HD){
    int h = col >> 7, kvh = h >> 2, g = h & 3;
    g_q[b*NKV + kvh][g*QL + qi][d] = out;
  } else {
    int kvh = (col - NH*HD) >> 7;
    g_kact[b*NKV + kvh][qi][d] = out;
  }
}

// ---------------- 3) split attention over PRIOR (exact R10/R13 best) ---------
__global__ __launch_bounds__(256) void attn_partial(
    const float* __restrict__ past_k, const float* __restrict__ past_v)
{
  int bk = blockIdx.y;       // b*NKV + kvh
  int sp = blockIdx.x;       // split
  int tid = threadIdx.x;
  int lane = tid & 31, wid = tid >> 5;

  __shared__ __align__(16) float qs[16][HD];     // scaled Q rows, 8KB
  __shared__ __align__(16) float ss[16][CHUNK];  // scores [row][key], 16KB
  __shared__ __align__(16) float red[8][8][HD];  // PV jslot partials, 32KB

  for (int i = tid; i < 16*HD; i += 256){
    int r = i >> 7, d = i & 127;
    qs[r][d] = g_q[bk][r][d] * SCALE;
  }
  __syncthreads();

  // ---- scores: 2 passes, 2 keys/thread; thread = (key group, 4-lane slice) --
  {
    int qt = tid & 3;          // dim slice within 4-lane group
    int keyg = tid >> 2;       // 0..63
    const float* Kbase = past_k + ((size_t)bk*PRIOR + (size_t)sp*CHUNK)*HD;
    #pragma unroll
    for (int p = 0; p < 2; p++){
      int j = p*128 + keyg;                 // keys j and j+64
      const ulonglong2* Kr0 = (const ulonglong2*)(Kbase + (size_t)j*HD) + qt;
      const ulonglong2* Kr1 = (const ulonglong2*)(Kbase + (size_t)(j+64)*HD) + qt;
      u64 acc0[16], acc1[16];
      #pragma unroll
      for (int r = 0; r < 16; r++){ acc0[r] = 0ull; acc1[r] = 0ull; }
      #pragma unroll 2
      for (int dd = 0; dd < 8; dd++){
        ulonglong2 ka = Kr0[dd*4];          // dims dd*16 + qt*4 ..+3
        ulonglong2 kb = Kr1[dd*4];
        int dim = dd*16 + qt*4;
        #pragma unroll
        for (int r = 0; r < 16; r++){
          ulonglong2 q2 = *(const ulonglong2*)&qs[r][dim];
          fma2(acc0[r], q2.x, ka.x);
          fma2(acc0[r], q2.y, ka.y);
          fma2(acc1[r], q2.x, kb.x);
          fma2(acc1[r], q2.y, kb.y);
        }
      }
      #pragma unroll
      for (int r = 0; r < 16; r++){
        float lo, hi; upk2(acc0[r], lo, hi);
        float s0 = lo + hi;
        upk2(acc1[r], lo, hi);
        float s1 = lo + hi;
        s0 += __shfl_xor_sync(~0u, s0, 1);
        s0 += __shfl_xor_sync(~0u, s0, 2);
        s1 += __shfl_xor_sync(~0u, s1, 1);
        s1 += __shfl_xor_sync(~0u, s1, 2);
        if (qt == 0){ ss[r][j] = s0; ss[r][j+64] = s1; }
      }
    }
  }
  __syncthreads();

  // ---- stats: warp owns 2 rows; max in registers; exp+sum one pass ---------
  #pragma unroll
  for (int rr = 0; rr < 2; rr++){
    int r = wid*2 + rr;
    float4* row = (float4*)ss[r];
    float4 a = row[lane], bq = row[lane+32];
    float m = fmaxf(fmaxf(fmaxf(a.x,a.y), fmaxf(a.z,a.w)),
                    fmaxf(fmaxf(bq.x,bq.y), fmaxf(bq.z,bq.w)));
    #pragma unroll
    for (int o = 16; o > 0; o >>= 1) m = fmaxf(m, __shfl_xor_sync(~0u, m, o));
    a.x = expf(a.x - m); a.y = expf(a.y - m); a.z = expf(a.z - m); a.w = expf(a.w - m);
    bq.x = expf(bq.x - m); bq.y = expf(bq.y - m); bq.z = expf(bq.z - m); bq.w = expf(bq.w - m);
    row[lane] = a; row[lane+32] = bq;
    float s = (a.x+a.y)+(a.z+a.w) + (bq.x+bq.y)+(bq.z+bq.w);
    #pragma unroll
    for (int o = 16; o > 0; o >>= 1) s += __shfl_xor_sync(~0u, s, o);
    if (lane == 0){ g_pm[bk][sp][r] = m; g_pl[bk][sp][r] = s; }
  }
  __syncthreads();

  // ---- PV: warp = (half, jslot); lane = 4-dim group -------------------------
  {
    int half = wid >> 2;          // rows half*8 .. +8
    int jslot = wid & 3;          // keys jslot*64 .. +64
    const float* Vb = past_v
        + ((size_t)bk*PRIOR + (size_t)sp*CHUNK + jslot*64)*HD + 4*lane;
    u64 acc[8][2];
    #pragma unroll
    for (int r = 0; r < 8; r++){ acc[r][0] = 0ull; acc[r][1] = 0ull; }

    for (int jj = 0; jj < 64; jj += 4){
      ulonglong2 w0 = *(const ulonglong2*)(Vb + (size_t)(jj+0)*HD);
      ulonglong2 w1 = *(const ulonglong2*)(Vb + (size_t)(jj+1)*HD);
      ulonglong2 w2 = *(const ulonglong2*)(Vb + (size_t)(jj+2)*HD);
      ulonglong2 w3 = *(const ulonglong2*)(Vb + (size_t)(jj+3)*HD);
      #pragma unroll
      for (int r = 0; r < 8; r++){
        ulonglong2 s4 = *(const ulonglong2*)&ss[half*8 + r][jslot*64 + jj];
        float s0, s1, s2, s3;
        upk2(s4.x, s0, s1); upk2(s4.y, s2, s3);
        u64 p0 = pk2(s0, s0), p1 = pk2(s1, s1);
        u64 p2 = pk2(s2, s2), p3 = pk2(s3, s3);
        fma2(acc[r][0], w0.x, p0); fma2(acc[r][1], w0.y, p0);
        fma2(acc[r][0], w1.x, p1); fma2(acc[r][1], w1.y, p1);
        fma2(acc[r][0], w2.x, p2); fma2(acc[r][1], w2.y, p2);
        fma2(acc[r][0], w3.x, p3); fma2(acc[r][1], w3.y, p3);
      }
    }
    #pragma unroll
    for (int r = 0; r < 8; r++){
      float4 o;
      upk2(acc[r][0], o.x, o.y);
      upk2(acc[r][1], o.z, o.w);
      *(float4*)&red[wid][r][4*lane] = o;
    }
  }
  __syncthreads();

  // ---- jslot reduction -> g_po ----------------------------------------------
  {
    int half2 = tid >> 7, d = tid & 127;
    #pragma unroll
    for (int r = 0; r < 8; r++){
      float o = red[half2*4+0][r][d] + red[half2*4+1][r][d]
              + red[half2*4+2][r][d] + red[half2*4+3][r][d];
      g_po[bk][sp][half2*8 + r][d] = o;
    }
  }
}

// ---------------- 4) LSE combine + active (causal) part ----------------------
__global__ __launch_bounds__(256) void attn_combine()
{
  int rg = blockIdx.x;       // 0..7 -> rows rg*2, rg*2+1
  int bk = blockIdx.y;
  int b = bk >> 3, kvh = bk & 7;
  int tid = threadIdx.x, lane = tid & 31, wid = tid >> 5;

  __shared__ float sc2[2][SPLITS], pa2[2][QL], invl[2];

  if (wid < 2){
    int r = rg*2 + wid, qi = r & 3;
    float m = (lane < SPLITS) ? g_pm[bk][lane][r] : -3.4e38f;
    #pragma unroll
    for (int o = 16; o > 0; o >>= 1) m = fmaxf(m, __shfl_xor_sync(~0u, m, o));
    float dots[QL];
    #pragma unroll
    for (int kq = 0; kq < QL; kq++){
      float a = g_q[bk][r][lane]      * g_kact[bk][kq][lane]
              + g_q[bk][r][lane+32]   * g_kact[bk][kq][lane+32]
              + g_q[bk][r][lane+64]   * g_kact[bk][kq][lane+64]
              + g_q[bk][r][lane+96]   * g_kact[bk][kq][lane+96];
      #pragma unroll
      for (int o = 16; o > 0; o >>= 1) a += __shfl_xor_sync(~0u, a, o);
      dots[kq] = a * SCALE;
      if (kq <= qi) m = fmaxf(m, dots[kq]);
    }
    float contrib = 0.f;
    if (lane < SPLITS){
      float e = expf(g_pm[bk][lane][r] - m);
      sc2[wid][lane] = e;
      contrib = g_pl[bk][lane][r] * e;
    }
    if (lane < QL){
      float ea = (lane <= qi) ? expf(dots[lane] - m) : 0.f;
      pa2[wid][lane] = ea;
      contrib += ea;
    }
    #pragma unroll
    for (int o = 16; o > 0; o >>= 1) contrib += __shfl_xor_sync(~0u, contrib, o);
    if (lane == 0) invl[wid] = 1.f / contrib;
  }
  __syncthreads();

  int half = tid >> 7, d = tid & 127;
  int r = rg*2 + half;
  float o = 0.f;
  #pragma unroll
  for (int s = 0; s < SPLITS; s++) o += g_po[bk][s][r][d] * sc2[half][s];
  #pragma unroll
  for (int kq = 0; kq < QL; kq++) o += pa2[half][kq] * g_vact[bk][kq][d];
  o *= invl[half];
  int g = r >> 2, qi2 = r & 3, h = kvh*GROUPS + g;
  g_ctx[b*QL + qi2][h*HD + d] = o;
}

// ---------------- 5) WO GEMV, K-split 32, float4 W loads, unroll 16 ----------
__global__ __launch_bounds__(256) void wo_gemm(const float* __restrict__ W)
{
  int ks = blockIdx.y;
  int k0 = ks * WO_KRANGE;
  int np = blockIdx.x * 256 + threadIdx.x;
  int n0 = np * 4;

  __shared__ __align__(16) float xs[WO_KRANGE][16];
  for (int i = threadIdx.x; i < WO_KRANGE*16; i += 256){
    int r = i >> 7, k = i & (WO_KRANGE-1);
    xs[k][r] = g_ctx[r][k0 + k];
  }
  __syncthreads();

  u64 acc[4][8];
  #pragma unroll
  for (int o = 0; o < 4; o++)
    #pragma unroll
    for (int i = 0; i < 8; i++) acc[o][i] = 0ull;

  const float4* Wp = (const float4*)(W + (size_t)k0 * HID + n0);
  const int ld4 = HID >> 2;
  #pragma unroll 16
  for (int k = 0; k < WO_KRANGE; k++){
    float4 w4 = *Wp; Wp += ld4;
    u64 wb[4];
    wb[0] = pk2(w4.x, w4.x); wb[1] = pk2(w4.y, w4.y);
    wb[2] = pk2(w4.z, w4.z); wb[3] = pk2(w4.w, w4.w);
    ulonglong2 xA = *(const ulonglong2*)&xs[k][0];
    ulonglong2 xB = *(const ulonglong2*)&xs[k][4];
    ulonglong2 xC = *(const ulonglong2*)&xs[k][8];
    ulonglong2 xD = *(const ulonglong2*)&xs[k][12];
    #pragma unroll
    for (int o = 0; o < 4; o++){
      fma2(acc[o][0], xA.x, wb[o]); fma2(acc[o][1], xA.y, wb[o]);
      fma2(acc[o][2], xB.x, wb[o]); fma2(acc[o][3], xB.y, wb[o]);
      fma2(acc[o][4], xC.x, wb[o]); fma2(acc[o][5], xC.y, wb[o]);
      fma2(acc[o][6], xD.x, wb[o]); fma2(acc[o][7], xD.y, wb[o]);
    }
  }
  #pragma unroll
  for (int i = 0; i < 8; i++){
    float lo[4], hi[4];
    #pragma unroll
    for (int o = 0; o < 4; o++) upk2(acc[o][i], lo[o], hi[o]);
    *(float4*)&g_wo_part[ks][2*i  ][n0] = make_float4(lo[0], lo[1], lo[2], lo[3]);
    *(float4*)&g_wo_part[ks][2*i+1][n0] = make_float4(hi[0], hi[1], hi[2], hi[3]);
  }
}

// ---------------- 6) reduce partials -> d_out --------------------------------
__global__ __launch_bounds__(256) void wo_reduce(float* __restrict__ out)
{
  int idx = blockIdx.x * 256 + threadIdx.x;  // 65536 total
  const float* base = (const float*)g_wo_part;
  float v = 0.f;
  #pragma unroll
  for (int s = 0; s < WO_KS; s++) v += base[(size_t)s * (NROWS*HID) + idx];
  out[idx] = v;
}

// ---------------- launch ------------------------------------------------------
extern "C" void kernel_launch(void* const* d_in, const int* in_sizes, int n_in,
                              void* d_out, int out_size)
{
  const float* hs     = (const float*)d_in[0];
  const float* past_k = (const float*)d_in[1];
  const float* past_v = (const float*)d_in[2];
  const float* wq     = (const float*)d_in[3];
  const float* wk     = (const float*)d_in[4];
  const float* wv     = (const float*)d_in[5];
  const float* wo     = (const float*)d_in[6];
  const int* pos_w    = (const int*)d_in[n_in - 1];   // int32 or int64 words
  float* out = (float*)d_out;

  qkv_gemm   <<<dim3(NQKV/1024, QKV_KS), 256>>>(hs, wq, wk, wv);
  rope_scatter<<<(NROWS*NQKV)/256, 256>>>(pos_w);
  attn_partial<<<dim3(SPLITS, B*NKV), 256>>>(past_k, past_v);
  attn_combine<<<dim3(8, B*NKV), 256>>>();
  wo_gemm    <<<dim3(HID/1024, WO_KS), 256>>>(wo);
  wo_reduce  <<<(NROWS*HID)/256, 256>>>(out);
}

// round 16
// speedup vs baseline: 1.1284x; 1.0347x over previous
#include <cuda_runtime.h>
#include <math.h>

#define B 4
#define QL 4
#define HID 4096
#define NH 32
#define NKV 8
#define HD 128
#define GROUPS 4
#define PRIOR 4096
#define NROWS 16              // B*QL token rows
#define NQKV 6144             // NH*HD + 2*NKV*HD
#define QKV_KS 32
#define QKV_KRANGE (HID/QKV_KS)   // 128
#define WO_KS 64
#define WO_KRANGE (HID/WO_KS)     // 64
#define SPLITS 16
#define CHUNK (PRIOR/SPLITS)      // 256
#define SCALE 0.08838834764831845f  // 1/sqrt(128)

// ---------------- scratch (static device globals; no runtime alloc) --------
__device__ float g_qkv_part[QKV_KS][NROWS][NQKV];
__device__ float g_q   [B*NKV][16][HD];
__device__ float g_kact[B*NKV][QL][HD];
__device__ float g_vact[B*NKV][QL][HD];
__device__ float g_po[B*NKV][SPLITS][16][HD];
__device__ float g_pm[B*NKV][SPLITS][16];
__device__ float g_pl[B*NKV][SPLITS][16];
__device__ float g_ctx[NROWS][NH*HD];
__device__ float g_wo_part[WO_KS][NROWS][HID];

typedef unsigned long long u64;

__device__ __forceinline__ u64 pk2(float lo, float hi){
  u64 r; asm("mov.b64 %0,{%1,%2};" : "=l"(r) : "f"(lo), "f"(hi)); return r;
}
__device__ __forceinline__ void upk2(u64 v, float& lo, float& hi){
  asm("mov.b64 {%0,%1},%2;" : "=f"(lo), "=f"(hi) : "l"(v));
}
__device__ __forceinline__ void fma2(u64& d, u64 a, u64 b){
  asm("fma.rn.f32x2 %0,%1,%2,%0;" : "+l"(d) : "l"(a), "l"(b));
}

// ---------------- 1) fused QKV GEMV, K-split 32, float4 W loads, unroll 16 ---
__global__ __launch_bounds__(256) void qkv_gemm(
    const float* __restrict__ X, const float* __restrict__ wq,
    const float* __restrict__ wk, const float* __restrict__ wv)
{
  int ks = blockIdx.y;
  int k0 = ks * QKV_KRANGE;
  int np = blockIdx.x * 256 + threadIdx.x;   // n-quad index
  int n0 = np * 4;
  const float* W; int nn, ldn;
  if (n0 < NH*HD)            { W = wq; nn = n0;              ldn = NH*HD;  }
  else if (n0 < NH*HD+NKV*HD){ W = wk; nn = n0 - NH*HD;      ldn = NKV*HD; }
  else                       { W = wv; nn = n0 - NH*HD - NKV*HD; ldn = NKV*HD; }

  __shared__ __align__(16) float xs[QKV_KRANGE][16];
  for (int i = threadIdx.x; i < QKV_KRANGE*16; i += 256){
    int r = i >> 7, k = i & (QKV_KRANGE-1);
    xs[k][r] = X[r*HID + k0 + k];
  }
  __syncthreads();

  u64 acc[4][8];
  #pragma unroll
  for (int o = 0; o < 4; o++)
    #pragma unroll
    for (int i = 0; i < 8; i++) acc[o][i] = 0ull;

  const float4* Wp = (const float4*)(W + (size_t)k0 * ldn + nn);
  int ld4 = ldn >> 2;
  #pragma unroll 16
  for (int k = 0; k < QKV_KRANGE; k++){
    float4 w4 = *Wp; Wp += ld4;
    u64 wb[4];
    wb[0] = pk2(w4.x, w4.x); wb[1] = pk2(w4.y, w4.y);
    wb[2] = pk2(w4.z, w4.z); wb[3] = pk2(w4.w, w4.w);
    ulonglong2 xA = *(const ulonglong2*)&xs[k][0];
    ulonglong2 xB = *(const ulonglong2*)&xs[k][4];
    ulonglong2 xC = *(const ulonglong2*)&xs[k][8];
    ulonglong2 xD = *(const ulonglong2*)&xs[k][12];
    #pragma unroll
    for (int o = 0; o < 4; o++){
      fma2(acc[o][0], xA.x, wb[o]); fma2(acc[o][1], xA.y, wb[o]);
      fma2(acc[o][2], xB.x, wb[o]); fma2(acc[o][3], xB.y, wb[o]);
      fma2(acc[o][4], xC.x, wb[o]); fma2(acc[o][5], xC.y, wb[o]);
      fma2(acc[o][6], xD.x, wb[o]); fma2(acc[o][7], xD.y, wb[o]);
    }
  }
  #pragma unroll
  for (int i = 0; i < 8; i++){
    float lo[4], hi[4];
    #pragma unroll
    for (int o = 0; o < 4; o++) upk2(acc[o][i], lo[o], hi[o]);
    *(float4*)&g_qkv_part[ks][2*i  ][n0] = make_float4(lo[0], lo[1], lo[2], lo[3]);
    *(float4*)&g_qkv_part[ks][2*i+1][n0] = make_float4(hi[0], hi[1], hi[2], hi[3]);
  }
}

// ---------------- 2) partial-reduce + RoPE (inline fp64) + scatter -----------
__global__ __launch_bounds__(256) void rope_scatter(const int* __restrict__ pos_w)
{
  int idx = blockIdx.x * 256 + threadIdx.x;     // 16*6144 total
  int row = idx / NQKV;
  int col = idx - row * NQKV;
  int b = row >> 2, qi = row & 3;

  float v = 0.f;
  #pragma unroll
  for (int s = 0; s < QKV_KS; s++) v += g_qkv_part[s][row][col];

  if (col >= NH*HD + NKV*HD){                   // V: no rope
    int c = col - (NH*HD + NKV*HD);
    int kvh = c >> 7, d = c & 127;
    g_vact[b*NKV + kvh][qi][d] = v;
    return;
  }
  int local = (col < NH*HD) ? col : col - NH*HD;
  int d = local & 127;
  int i = d & 63;
  int stride = (pos_w[1] == 0) ? 2 : 1;         // int64 (LE words) vs int32
  int p = pos_w[(b*QL + qi) * stride];
  double invf = exp(-((double)i / 64.0) * 13.815510557964274);  // 1e6^(-i/64)
  double ds, dc; sincos((double)p * invf, &ds, &dc);
  float c_ = (float)dc, s_ = (float)ds;

  int ocol = (d < 64) ? col + 64 : col - 64;
  float ov = 0.f;
  #pragma unroll
  for (int s = 0; s < QKV_KS; s++) ov += g_qkv_part[s][row][ocol];

  float out = (d < 64) ? (v*c_ - ov*s_) : (v*c_ + ov*s_);
  if (col < NH*HD){
    int h = col >> 7, kvh = h >> 2, g = h & 3;
    g_q[b*NKV + kvh][g*QL + qi][d] = out;
  } else {
    int kvh = (col - NH*HD) >> 7;
    g_kact[b*NKV + kvh][qi][d] = out;
  }
}

// ---------------- 3) split attention over PRIOR ------------------------------
// R13 structure; dd unroll 4 (8 K loads in flight), PV j unroll 8 (8 V loads).
__global__ __launch_bounds__(256) void attn_partial(
    const float* __restrict__ past_k, const float* __restrict__ past_v)
{
  int bk = blockIdx.y;       // b*NKV + kvh
  int sp = blockIdx.x;       // split
  int tid = threadIdx.x;
  int lane = tid & 31, wid = tid >> 5;

  __shared__ __align__(16) float qs[16][HD];     // scaled Q rows, 8KB
  __shared__ __align__(16) float ss[16][CHUNK];  // scores [row][key], 16KB
  __shared__ __align__(16) float red[8][8][HD];  // PV jslot partials, 32KB

  for (int i = tid; i < 16*HD; i += 256){
    int r = i >> 7, d = i & 127;
    qs[r][d] = g_q[bk][r][d] * SCALE;
  }
  __syncthreads();

  // ---- scores: 2 passes, 2 keys/thread; thread = (key group, 4-lane slice) --
  {
    int qt = tid & 3;          // dim slice within 4-lane group
    int keyg = tid >> 2;       // 0..63
    const float* Kbase = past_k + ((size_t)bk*PRIOR + (size_t)sp*CHUNK)*HD;
    #pragma unroll
    for (int p = 0; p < 2; p++){
      int j = p*128 + keyg;                 // keys j and j+64
      const ulonglong2* Kr0 = (const ulonglong2*)(Kbase + (size_t)j*HD) + qt;
      const ulonglong2* Kr1 = (const ulonglong2*)(Kbase + (size_t)(j+64)*HD) + qt;
      u64 acc0[16], acc1[16];
      #pragma unroll
      for (int r = 0; r < 16; r++){ acc0[r] = 0ull; acc1[r] = 0ull; }
      #pragma unroll 4
      for (int dd = 0; dd < 8; dd++){
        ulonglong2 ka = Kr0[dd*4];          // dims dd*16 + qt*4 ..+3
        ulonglong2 kb = Kr1[dd*4];
        int dim = dd*16 + qt*4;
        #pragma unroll
        for (int r = 0; r < 16; r++){
          ulonglong2 q2 = *(const ulonglong2*)&qs[r][dim];
          fma2(acc0[r], q2.x, ka.x);
          fma2(acc0[r], q2.y, ka.y);
          fma2(acc1[r], q2.x, kb.x);
          fma2(acc1[r], q2.y, kb.y);
        }
      }
      #pragma unroll
      for (int r = 0; r < 16; r++){
        float lo, hi; upk2(acc0[r], lo, hi);
        float s0 = lo + hi;
        upk2(acc1[r], lo, hi);
        float s1 = lo + hi;
        s0 += __shfl_xor_sync(~0u, s0, 1);
        s0 += __shfl_xor_sync(~0u, s0, 2);
        s1 += __shfl_xor_sync(~0u, s1, 1);
        s1 += __shfl_xor_sync(~0u, s1, 2);
        if (qt == 0){ ss[r][j] = s0; ss[r][j+64] = s1; }
      }
    }
  }
  __syncthreads();

  // ---- stats: warp owns 2 rows; max in registers; exp+sum one pass ---------
  #pragma unroll
  for (int rr = 0; rr < 2; rr++){
    int r = wid*2 + rr;
    float4* row = (float4*)ss[r];
    float4 a = row[lane], bq = row[lane+32];
    float m = fmaxf(fmaxf(fmaxf(a.x,a.y), fmaxf(a.z,a.w)),
                    fmaxf(fmaxf(bq.x,bq.y), fmaxf(bq.z,bq.w)));
    #pragma unroll
    for (int o = 16; o > 0; o >>= 1) m = fmaxf(m, __shfl_xor_sync(~0u, m, o));
    a.x = expf(a.x - m); a.y = expf(a.y - m); a.z = expf(a.z - m); a.w = expf(a.w - m);
    bq.x = expf(bq.x - m); bq.y = expf(bq.y - m); bq.z = expf(bq.z - m); bq.w = expf(bq.w - m);
    row[lane] = a; row[lane+32] = bq;
    float s = (a.x+a.y)+(a.z+a.w) + (bq.x+bq.y)+(bq.z+bq.w);
    #pragma unroll
    for (int o = 16; o > 0; o >>= 1) s += __shfl_xor_sync(~0u, s, o);
    if (lane == 0){ g_pm[bk][sp][r] = m; g_pl[bk][sp][r] = s; }
  }
  __syncthreads();

  // ---- PV: warp = (half, jslot); lane = 4-dim group; j unroll 8 -------------
  {
    int half = wid >> 2;          // rows half*8 .. +8
    int jslot = wid & 3;          // keys jslot*64 .. +64
    const float* Vb = past_v
        + ((size_t)bk*PRIOR + (size_t)sp*CHUNK + jslot*64)*HD + 4*lane;
    u64 acc[8][2];
    #pragma unroll
    for (int r = 0; r < 8; r++){ acc[r][0] = 0ull; acc[r][1] = 0ull; }

    for (int jj = 0; jj < 64; jj += 8){
      ulonglong2 w0 = *(const ulonglong2*)(Vb + (size_t)(jj+0)*HD);
      ulonglong2 w1 = *(const ulonglong2*)(Vb + (size_t)(jj+1)*HD);
      ulonglong2 w2 = *(const ulonglong2*)(Vb + (size_t)(jj+2)*HD);
      ulonglong2 w3 = *(const ulonglong2*)(Vb + (size_t)(jj+3)*HD);
      ulonglong2 w4 = *(const ulonglong2*)(Vb + (size_t)(jj+4)*HD);
      ulonglong2 w5 = *(const ulonglong2*)(Vb + (size_t)(jj+5)*HD);
      ulonglong2 w6 = *(const ulonglong2*)(Vb + (size_t)(jj+6)*HD);
      ulonglong2 w7 = *(const ulonglong2*)(Vb + (size_t)(jj+7)*HD);
      #pragma unroll
      for (int r = 0; r < 8; r++){
        ulonglong2 sa = *(const ulonglong2*)&ss[half*8 + r][jslot*64 + jj];
        ulonglong2 sb = *(const ulonglong2*)&ss[half*8 + r][jslot*64 + jj + 4];
        float s0, s1, s2, s3, s4, s5, s6, s7;
        upk2(sa.x, s0, s1); upk2(sa.y, s2, s3);
        upk2(sb.x, s4, s5); upk2(sb.y, s6, s7);
        u64 p0 = pk2(s0, s0), p1 = pk2(s1, s1);
        u64 p2 = pk2(s2, s2), p3 = pk2(s3, s3);
        u64 p4 = pk2(s4, s4), p5 = pk2(s5, s5);
        u64 p6 = pk2(s6, s6), p7 = pk2(s7, s7);
        fma2(acc[r][0], w0.x, p0); fma2(acc[r][1], w0.y, p0);
        fma2(acc[r][0], w1.x, p1); fma2(acc[r][1], w1.y, p1);
        fma2(acc[r][0], w2.x, p2); fma2(acc[r][1], w2.y, p2);
        fma2(acc[r][0], w3.x, p3); fma2(acc[r][1], w3.y, p3);
        fma2(acc[r][0], w4.x, p4); fma2(acc[r][1], w4.y, p4);
        fma2(acc[r][0], w5.x, p5); fma2(acc[r][1], w5.y, p5);
        fma2(acc[r][0], w6.x, p6); fma2(acc[r][1], w6.y, p6);
        fma2(acc[r][0], w7.x, p7); fma2(acc[r][1], w7.y, p7);
      }
    }
    #pragma unroll
    for (int r = 0; r < 8; r++){
      float4 o;
      upk2(acc[r][0], o.x, o.y);
      upk2(acc[r][1], o.z, o.w);
      *(float4*)&red[wid][r][4*lane] = o;
    }
  }
  __syncthreads();

  // ---- jslot reduction -> g_po ----------------------------------------------
  {
    int half2 = tid >> 7, d = tid & 127;
    #pragma unroll
    for (int r = 0; r < 8; r++){
      float o = red[half2*4+0][r][d] + red[half2*4+1][r][d]
              + red[half2*4+2][r][d] + red[half2*4+3][r][d];
      g_po[bk][sp][half2*8 + r][d] = o;
    }
  }
}

// ---------------- 4) LSE combine + active (causal) part ----------------------
__global__ __launch_bounds__(256) void attn_combine()
{
  int rg = blockIdx.x;       // 0..7 -> rows rg*2, rg*2+1
  int bk = blockIdx.y;
  int b = bk >> 3, kvh = bk & 7;
  int tid = threadIdx.x, lane = tid & 31, wid = tid >> 5;

  __shared__ float sc2[2][SPLITS], pa2[2][QL], invl[2];

  if (wid < 2){
    int r = rg*2 + wid, qi = r & 3;
    float m = (lane < SPLITS) ? g_pm[bk][lane][r] : -3.4e38f;
    #pragma unroll
    for (int o = 16; o > 0; o >>= 1) m = fmaxf(m, __shfl_xor_sync(~0u, m, o));
    float dots[QL];
    #pragma unroll
    for (int kq = 0; kq < QL; kq++){
      float a = g_q[bk][r][lane]      * g_kact[bk][kq][lane]
              + g_q[bk][r][lane+32]   * g_kact[bk][kq][lane+32]
              + g_q[bk][r][lane+64]   * g_kact[bk][kq][lane+64]
              + g_q[bk][r][lane+96]   * g_kact[bk][kq][lane+96];
      #pragma unroll
      for (int o = 16; o > 0; o >>= 1) a += __shfl_xor_sync(~0u, a, o);
      dots[kq] = a * SCALE;
      if (kq <= qi) m = fmaxf(m, dots[kq]);
    }
    float contrib = 0.f;
    if (lane < SPLITS){
      float e = expf(g_pm[bk][lane][r] - m);
      sc2[wid][lane] = e;
      contrib = g_pl[bk][lane][r] * e;
    }
    if (lane < QL){
      float ea = (lane <= qi) ? expf(dots[lane] - m) : 0.f;
      pa2[wid][lane] = ea;
      contrib += ea;
    }
    #pragma unroll
    for (int o = 16; o > 0; o >>= 1) contrib += __shfl_xor_sync(~0u, contrib, o);
    if (lane == 0) invl[wid] = 1.f / contrib;
  }
  __syncthreads();

  int half = tid >> 7, d = tid & 127;
  int r = rg*2 + half;
  float o = 0.f;
  #pragma unroll
  for (int s = 0; s < SPLITS; s++) o += g_po[bk][s][r][d] * sc2[half][s];
  #pragma unroll
  for (int kq = 0; kq < QL; kq++) o += pa2[half][kq] * g_vact[bk][kq][d];
  o *= invl[half];
  int g = r >> 2, qi2 = r & 3, h = kvh*GROUPS + g;
  g_ctx[b*QL + qi2][h*HD + d] = o;
}

// ---------------- 5) WO GEMV, K-split 64, float4 W loads, unroll 16 ----------
__global__ __launch_bounds__(256) void wo_gemm(const float* __restrict__ W)
{
  int ks = blockIdx.y;
  int k0 = ks * WO_KRANGE;
  int np = blockIdx.x * 256 + threadIdx.x;
  int n0 = np * 4;

  __shared__ __align__(16) float xs[WO_KRANGE][16];
  for (int i = threadIdx.x; i < WO_KRANGE*16; i += 256){
    int r = i >> 6, k = i & (WO_KRANGE-1);
    xs[k][r] = g_ctx[r][k0 + k];
  }
  __syncthreads();

  u64 acc[4][8];
  #pragma unroll
  for (int o = 0; o < 4; o++)
    #pragma unroll
    for (int i = 0; i < 8; i++) acc[o][i] = 0ull;

  const float4* Wp = (const float4*)(W + (size_t)k0 * HID + n0);
  const int ld4 = HID >> 2;
  #pragma unroll 16
  for (int k = 0; k < WO_KRANGE; k++){
    float4 w4 = *Wp; Wp += ld4;
    u64 wb[4];
    wb[0] = pk2(w4.x, w4.x); wb[1] = pk2(w4.y, w4.y);
    wb[2] = pk2(w4.z, w4.z); wb[3] = pk2(w4.w, w4.w);
    ulonglong2 xA = *(const ulonglong2*)&xs[k][0];
    ulonglong2 xB = *(const ulonglong2*)&xs[k][4];
    ulonglong2 xC = *(const ulonglong2*)&xs[k][8];
    ulonglong2 xD = *(const ulonglong2*)&xs[k][12];
    #pragma unroll
    for (int o = 0; o < 4; o++){
      fma2(acc[o][0], xA.x, wb[o]); fma2(acc[o][1], xA.y, wb[o]);
      fma2(acc[o][2], xB.x, wb[o]); fma2(acc[o][3], xB.y, wb[o]);
      fma2(acc[o][4], xC.x, wb[o]); fma2(acc[o][5], xC.y, wb[o]);
      fma2(acc[o][6], xD.x, wb[o]); fma2(acc[o][7], xD.y, wb[o]);
    }
  }
  #pragma unroll
  for (int i = 0; i < 8; i++){
    float lo[4], hi[4];
    #pragma unroll
    for (int o = 0; o < 4; o++) upk2(acc[o][i], lo[o], hi[o]);
    *(float4*)&g_wo_part[ks][2*i  ][n0] = make_float4(lo[0], lo[1], lo[2], lo[3]);
    *(float4*)&g_wo_part[ks][2*i+1][n0] = make_float4(hi[0], hi[1], hi[2], hi[3]);
  }
}

// ---------------- 6) reduce partials -> d_out --------------------------------
__global__ __launch_bounds__(256) void wo_reduce(float* __restrict__ out)
{
  int idx = blockIdx.x * 256 + threadIdx.x;  // 65536 total
  const float* base = (const float*)g_wo_part;
  float v = 0.f;
  #pragma unroll
  for (int s = 0; s < WO_KS; s++) v += base[(size_t)s * (NROWS*HID) + idx];
  out[idx] = v;
}

// ---------------- launch ------------------------------------------------------
extern "C" void kernel_launch(void* const* d_in, const int* in_sizes, int n_in,
                              void* d_out, int out_size)
{
  const float* hs     = (const float*)d_in[0];
  const float* past_k = (const float*)d_in[1];
  const float* past_v = (const float*)d_in[2];
  const float* wq     = (const float*)d_in[3];
  const float* wk     = (const float*)d_in[4];
  const float* wv     = (const float*)d_in[5];
  const float* wo     = (const float*)d_in[6];
  const int* pos_w    = (const int*)d_in[n_in - 1];   // int32 or int64 words
  float* out = (float*)d_out;

  qkv_gemm   <<<dim3(NQKV/1024, QKV_KS), 256>>>(hs, wq, wk, wv);
  rope_scatter<<<(NROWS*NQKV)/256, 256>>>(pos_w);
  attn_partial<<<dim3(SPLITS, B*NKV), 256>>>(past_k, past_v);
  attn_combine<<<dim3(8, B*NKV), 256>>>();
  wo_gemm    <<<dim3(HID/1024, WO_KS), 256>>>(wo);
  wo_reduce  <<<(NROWS*HID)/256, 256>>>(out);
}